// round 16
// baseline (speedup 1.0000x reference)
#include <cuda_runtime.h>
#include <cuda_fp16.h>
#include <math.h>
#include <stdint.h>

#define N_EMBED 1024
#define SLEN    2048
#define BATCH   4
#define NHEADS  16
#define HDIM    64
#define MROWS   (BATCH * SLEN)        // 8192

// Scratch (device globals: allocation-free rule)
__device__ __half g_qh[(size_t)MROWS * N_EMBED];        // Q half (scaled 1/8)
__device__ __half g_kh[(size_t)MROWS * N_EMBED];        // K half
__device__ __half g_vh[(size_t)MROWS * N_EMBED];        // V half
__device__ __half g_yh[(size_t)MROWS * N_EMBED];        // attention out half
__device__ __half g_xh[(size_t)MROWS * N_EMBED];        // x half
__device__ __half g_wa[(size_t)3 * N_EMBED * N_EMBED];  // Wattn^T half [3072,1024]
__device__ __half g_wp[(size_t)N_EMBED * N_EMBED];      // Wproj^T half [1024,1024]
__device__ int    g_work;                               // attention work counter

// ---------------------------------------------------------------------------
// Helpers
// ---------------------------------------------------------------------------
__device__ __forceinline__ void mma_f16(float d[4], const uint32_t a[4], const uint32_t b[2]) {
    asm volatile(
        "mma.sync.aligned.m16n8k16.row.col.f32.f16.f16.f32 "
        "{%0,%1,%2,%3}, {%4,%5,%6,%7}, {%8,%9}, {%0,%1,%2,%3};"
        : "+f"(d[0]), "+f"(d[1]), "+f"(d[2]), "+f"(d[3])
        : "r"(a[0]), "r"(a[1]), "r"(a[2]), "r"(a[3]), "r"(b[0]), "r"(b[1]));
}
__device__ __forceinline__ uint32_t smem_u32(const void* p) {
    uint32_t a;
    asm("{ .reg .u64 t; cvta.to.shared.u64 t, %1; cvt.u32.u64 %0, t; }" : "=r"(a) : "l"(p));
    return a;
}
__device__ __forceinline__ void cp_async16(uint32_t saddr, const void* g) {
    asm volatile("cp.async.cg.shared.global [%0], [%1], 16;" :: "r"(saddr), "l"(g));
}
#define CP_COMMIT()  asm volatile("cp.async.commit_group;" ::: "memory")
#define CP_WAIT(n)   asm volatile("cp.async.wait_group %0;" :: "n"(n) : "memory")
__device__ __forceinline__ uint32_t pack_h2(float x, float y) {
    __half2 h = __floats2half2_rn(x, y);
    return *reinterpret_cast<uint32_t*>(&h);
}

// ---------------------------------------------------------------------------
// fp32 -> half elementwise (x), grid-stride. Also resets the work counter.
// ---------------------------------------------------------------------------
__global__ __launch_bounds__(256)
void cvt_half_kernel(const float* __restrict__ in, __half* __restrict__ out, int n,
                     int* __restrict__ work) {
    if (blockIdx.x == 0 && threadIdx.x == 0 && work) *work = 0;
    const int stride = gridDim.x * blockDim.x * 4;
    for (int i = (blockIdx.x * blockDim.x + threadIdx.x) * 4; i < n; i += stride) {
        float4 v = *reinterpret_cast<const float4*>(in + i);
        uint2 o;
        o.x = pack_h2(v.x, v.y);
        o.y = pack_h2(v.z, v.w);
        *reinterpret_cast<uint2*>(out + i) = o;
    }
}

// ---------------------------------------------------------------------------
// Transpose + cvt: out[c][r] = (half) in[r][c].
// ---------------------------------------------------------------------------
__global__ __launch_bounds__(256)
void transpose_half_kernel(const float* __restrict__ in, __half* __restrict__ out,
                           int R, int C) {
    __shared__ float t[32][33];
    const int c0 = blockIdx.x * 32, r0 = blockIdx.y * 32;
    const int tx = threadIdx.x, ty = threadIdx.y;   // 32 x 8
    #pragma unroll
    for (int i = ty; i < 32; i += 8)
        t[i][tx] = in[(size_t)(r0 + i) * C + c0 + tx];
    __syncthreads();
    #pragma unroll
    for (int i = ty; i < 32; i += 8)
        out[(size_t)(c0 + i) * R + r0 + tx] = __float2half_rn(t[tx][i]);
}

// ---------------------------------------------------------------------------
// fp16 mma.sync GEMM (R11-proven): C = A[M,K] @ Bt[N,K]^T + bias.
// mode 0: C fp32.  mode 1 (QKV): Q->qh (x1/8); K->kh; V->vh (all half).
// BM=BN=128, BK=32; 256 thr = 8 warps (2x4), warp tile 64x32; 4-stage cp.async.
// ---------------------------------------------------------------------------
#define G_RS 40
#define G_RSW 20
#define G_TSTG (128 * G_RS)
#define G_STG_HALFS (2 * G_TSTG)
#define G_SMEM_BYTES (4 * G_STG_HALFS * 2)

__global__ __launch_bounds__(256, 2)
void mma_gemm_kernel(const __half* __restrict__ A, const __half* __restrict__ Bt,
                     const float* __restrict__ bias, float* __restrict__ C,
                     __half* qh, __half* kh, __half* vh,
                     int M, int N, int K, int mode) {
    extern __shared__ uint32_t gsm[];

    const int tid   = threadIdx.x;
    const int lane  = tid & 31;
    const int wid   = tid >> 5;
    const int gid   = lane >> 2;
    const int tig   = lane & 3;
    const int warpM = wid >> 2;
    const int warpN = wid & 3;
    const int row0  = blockIdx.y * 128;
    const int col0  = blockIdx.x * 128;

    const uint32_t uS = smem_u32(gsm);
    const int lrow = tid >> 1;
    const int lch  = (tid & 1) * 2;

    auto issue = [&](int kt, int stg) {
        const __half* Ag = A  + (size_t)(row0 + lrow) * K + kt * 32;
        const __half* Bg = Bt + (size_t)(col0 + lrow) * K + kt * 32;
        const uint32_t sa = uS + (uint32_t)(stg * G_STG_HALFS + lrow * G_RS) * 2;
        const uint32_t sb = sa + (uint32_t)G_TSTG * 2;
        #pragma unroll
        for (int i = 0; i < 2; i++) {
            const int c = lch + i;
            cp_async16(sa + c * 16, Ag + c * 8);
            cp_async16(sb + c * 16, Bg + c * 8);
        }
        CP_COMMIT();
    };

    float acc[4][4][4];
    #pragma unroll
    for (int i = 0; i < 4; i++)
        #pragma unroll
        for (int j = 0; j < 4; j++)
            #pragma unroll
            for (int r = 0; r < 4; r++) acc[i][j][r] = 0.f;

    const int NT = K / 32;

    issue(0, 0); issue(1, 1); issue(2, 2);

    for (int kt = 0; kt < NT; kt++) {
        if (kt < NT - 2) { CP_WAIT(2); } else { CP_WAIT(0); }
        __syncthreads();

        const uint32_t* As = gsm + (kt & 3) * (G_STG_HALFS / 2);
        const uint32_t* Bs = As + (G_TSTG / 2);

        #pragma unroll
        for (int ks = 0; ks < 2; ks++) {
            const int kw = ks * 8;
            uint32_t a[4][4], b[4][2];
            #pragma unroll
            for (int mf = 0; mf < 4; mf++) {
                const int r = warpM * 64 + mf * 16;
                a[mf][0] = As[(r + gid)     * G_RSW + kw + tig];
                a[mf][1] = As[(r + gid + 8) * G_RSW + kw + tig];
                a[mf][2] = As[(r + gid)     * G_RSW + kw + tig + 4];
                a[mf][3] = As[(r + gid + 8) * G_RSW + kw + tig + 4];
            }
            #pragma unroll
            for (int nf = 0; nf < 4; nf++) {
                const int c = warpN * 32 + nf * 8 + gid;
                b[nf][0] = Bs[c * G_RSW + kw + tig];
                b[nf][1] = Bs[c * G_RSW + kw + tig + 4];
            }
            #pragma unroll
            for (int mf = 0; mf < 4; mf++)
                #pragma unroll
                for (int nf = 0; nf < 4; nf++)
                    mma_f16(acc[mf][nf], a[mf], b[nf]);
        }
        if (kt + 3 < NT) issue(kt + 3, (kt + 3) & 3);
    }

    #pragma unroll
    for (int mf = 0; mf < 4; mf++) {
        const size_t rb0 = (size_t)row0 + warpM * 64 + mf * 16 + gid;
        const size_t rb1 = rb0 + 8;
        #pragma unroll
        for (int nf = 0; nf < 4; nf++) {
            const int col = col0 + warpN * 32 + nf * 8 + tig * 2;
            const float2 bz = *reinterpret_cast<const float2*>(bias + col);
            const float o00 = acc[mf][nf][0] + bz.x, o01 = acc[mf][nf][1] + bz.y;
            const float o10 = acc[mf][nf][2] + bz.x, o11 = acc[mf][nf][3] + bz.y;
            if (mode == 0) {
                float2 v0, v1;
                v0.x = o00; v0.y = o01; v1.x = o10; v1.y = o11;
                *reinterpret_cast<float2*>(C + rb0 * N + col) = v0;
                *reinterpret_cast<float2*>(C + rb1 * N + col) = v1;
            } else if (col0 < 1024) {
                *reinterpret_cast<uint32_t*>(&qh[rb0 * N_EMBED + col]) =
                    pack_h2(o00 * 0.125f, o01 * 0.125f);
                *reinterpret_cast<uint32_t*>(&qh[rb1 * N_EMBED + col]) =
                    pack_h2(o10 * 0.125f, o11 * 0.125f);
            } else if (col0 < 2048) {
                const int c = col - 1024;
                *reinterpret_cast<uint32_t*>(&kh[rb0 * N_EMBED + c]) = pack_h2(o00, o01);
                *reinterpret_cast<uint32_t*>(&kh[rb1 * N_EMBED + c]) = pack_h2(o10, o11);
            } else {
                const int c = col - 2048;
                *reinterpret_cast<uint32_t*>(&vh[rb0 * N_EMBED + c]) = pack_h2(o00, o01);
                *reinterpret_cast<uint32_t*>(&vh[rb1 * N_EMBED + c]) = pack_h2(o10, o11);
            }
        }
    }
}

// ---------------------------------------------------------------------------
// Flash attention, fp16 MMAs (single-term QK), cp.async staging,
// ldmatrix.trans for V.  PERSISTENT kernel: 296 CTAs pop 64-row q-tiles
// (heavy-first) from a global counter until the 2048-item queue is drained.
// Per tile: 64 q-rows; 4 warps (128 thr); 64-key chunks; 2 CTAs/SM.
// SMEM halfs (rows of 72):
//   K0 @0 | V0 @4608 | K1 @9216 | V1 @13824 | Ps @18432   (23040 halfs)
//   Q overlay per tile: Qh @0 (over K0).
// ---------------------------------------------------------------------------
#define AH 72
#define AHW 36
#define FA_SMEM_BYTES 46080
#define N_ITEMS (32 * NHEADS * BATCH)   // 2048

__global__ __launch_bounds__(128, 2)
void flash_attn_mma_kernel(const __half* __restrict__ qhg,
                           const __half* __restrict__ kh, const __half* __restrict__ vh,
                           __half* __restrict__ y, int* __restrict__ work) {
    extern __shared__ __half sh[];
    uint32_t* shw = reinterpret_cast<uint32_t*>(sh);
    const uint32_t uS = smem_u32(sh);
    __shared__ int s_item;

    const int tid = threadIdx.x;
    const int lane = tid & 31;
    const int wid  = tid >> 5;     // 0..3
    const int gid  = lane >> 2;
    const int tig  = lane & 3;
    const int wrow = wid * 16;

    const int srow = tid >> 1;          // staging row 0..63
    const int sch  = (tid & 1) * 4;     // 4 chunks of 16B each

    uint32_t* Psw = shw + 9216;   // word base of Ps

    // ldmatrix.trans lane-fixed addressing for V
    const int lm  = lane >> 3;
    const int lrw = lane & 7;
    const int km  = ((lm & 1) << 3) + lrw;
    const int cm  = (lm >> 1) * 8;

    for (;;) {
        if (tid == 0) s_item = atomicAdd(work, 1);
        __syncthreads();   // broadcast item; also orders prior tile's smem reads
        const int idx = s_item;
        if (idx >= N_ITEMS) break;

        // heavy-first: items 0..63 -> qt=31, 64..127 -> qt=30, ...
        const int qt = 31 - (idx >> 6);
        const int hb = idx & 63;
        const int h  = hb & 15;
        const int b  = hb >> 4;
        const int q0 = qt * 64;
        const int nch = qt + 1;
        const size_t rowbase = (size_t)b * SLEN;
        const int hofs = h * 64;

        // ---- Q staging (cp.async into overlay over K0) ----
        {
            const __half* gq = qhg + (rowbase + q0 + srow) * N_EMBED + hofs;
            const uint32_t dq = uS + (uint32_t)(srow * AH) * 2;
            #pragma unroll
            for (int i = 0; i < 4; i++)
                cp_async16(dq + (sch + i) * 16, gq + (sch + i) * 8);
            CP_COMMIT();
            CP_WAIT(0);
        }
        __syncthreads();

        // ---- Q fragments (4 k16-steps over 64 dims) ----
        uint32_t qh[4][4];
        #pragma unroll
        for (int ks = 0; ks < 4; ks++) {
            const int ba = (wrow + gid) * AHW + ks * 8;
            const int bb = (wrow + gid + 8) * AHW + ks * 8;
            qh[ks][0] = shw[ba + tig];     qh[ks][1] = shw[bb + tig];
            qh[ks][2] = shw[ba + tig + 4]; qh[ks][3] = shw[bb + tig + 4];
        }
        __syncthreads();   // all warps done with overlay before K/V cp.async lands

        auto issue_kv = [&](int kb, int buf) {
            const __half* gk = kh + (rowbase + kb + srow) * N_EMBED + hofs;
            const __half* gv = vh + (rowbase + kb + srow) * N_EMBED + hofs;
            const uint32_t dk = uS + (uint32_t)(buf * 9216 + srow * AH) * 2;
            const uint32_t dv = dk + 4608 * 2;
            #pragma unroll
            for (int i = 0; i < 4; i++) {
                cp_async16(dk + (sch + i) * 16, gk + (sch + i) * 8);
                cp_async16(dv + (sch + i) * 16, gv + (sch + i) * 8);
            }
            CP_COMMIT();
        };

        issue_kv(0, 0);

        float oacc[8][4];
        #pragma unroll
        for (int nf = 0; nf < 8; nf++)
            #pragma unroll
            for (int e = 0; e < 4; e++) oacc[nf][e] = 0.f;
        float m0 = -INFINITY, m1 = -INFINITY, l0 = 0.f, l1 = 0.f;

        const int row0g = q0 + wrow + gid;
        const int row1g = row0g + 8;

        for (int i = 0; i < nch; i++) {
            const int buf = i & 1;
            const int kb  = i * 64;
            if (i + 1 < nch) { issue_kv(kb + 64, buf ^ 1); CP_WAIT(1); }
            else             { CP_WAIT(0); }
            __syncthreads();

            const uint32_t* Kw = shw + buf * 4608;

            // ---- S = Q K^T ----
            float sacc[8][4];
            #pragma unroll
            for (int nf = 0; nf < 8; nf++)
                #pragma unroll
                for (int e = 0; e < 4; e++) sacc[nf][e] = 0.f;

            #pragma unroll
            for (int ks = 0; ks < 4; ks++) {
                #pragma unroll
                for (int nf = 0; nf < 8; nf++) {
                    const int kr = (nf * 8 + gid) * AHW + ks * 8;
                    uint32_t bh[2];
                    bh[0] = Kw[kr + tig]; bh[1] = Kw[kr + tig + 4];
                    mma_f16(sacc[nf], qh[ks], bh);
                }
            }

            // ---- causal mask (diagonal chunk only) ----
            if (kb + 63 > q0 + wrow) {
                #pragma unroll
                for (int nf = 0; nf < 8; nf++) {
                    const int c = kb + nf * 8 + tig * 2;
                    if (c     > row0g) sacc[nf][0] = -INFINITY;
                    if (c + 1 > row0g) sacc[nf][1] = -INFINITY;
                    if (c     > row1g) sacc[nf][2] = -INFINITY;
                    if (c + 1 > row1g) sacc[nf][3] = -INFINITY;
                }
            }

            // ---- online softmax ----
            float mx0 = -INFINITY, mx1 = -INFINITY;
            #pragma unroll
            for (int nf = 0; nf < 8; nf++) {
                mx0 = fmaxf(mx0, fmaxf(sacc[nf][0], sacc[nf][1]));
                mx1 = fmaxf(mx1, fmaxf(sacc[nf][2], sacc[nf][3]));
            }
            mx0 = fmaxf(mx0, __shfl_xor_sync(0xffffffff, mx0, 1));
            mx0 = fmaxf(mx0, __shfl_xor_sync(0xffffffff, mx0, 2));
            mx1 = fmaxf(mx1, __shfl_xor_sync(0xffffffff, mx1, 1));
            mx1 = fmaxf(mx1, __shfl_xor_sync(0xffffffff, mx1, 2));

            const float mn0 = fmaxf(m0, mx0);
            const float mn1 = fmaxf(m1, mx1);
            const float a0 = __expf(m0 - mn0);
            const float a1 = __expf(m1 - mn1);
            m0 = mn0; m1 = mn1;

            float rs0 = 0.f, rs1 = 0.f;
            #pragma unroll
            for (int nf = 0; nf < 8; nf++) {
                const float p0 = __expf(sacc[nf][0] - m0);
                const float p1 = __expf(sacc[nf][1] - m0);
                const float p2 = __expf(sacc[nf][2] - m1);
                const float p3 = __expf(sacc[nf][3] - m1);
                rs0 += p0 + p1; rs1 += p2 + p3;
                Psw[(wrow + gid)     * AHW + nf * 4 + tig] = pack_h2(p0, p1);
                Psw[(wrow + gid + 8) * AHW + nf * 4 + tig] = pack_h2(p2, p3);
            }
            rs0 += __shfl_xor_sync(0xffffffff, rs0, 1);
            rs0 += __shfl_xor_sync(0xffffffff, rs0, 2);
            rs1 += __shfl_xor_sync(0xffffffff, rs1, 1);
            rs1 += __shfl_xor_sync(0xffffffff, rs1, 2);
            l0 = l0 * a0 + rs0;
            l1 = l1 * a1 + rs1;

            #pragma unroll
            for (int nf = 0; nf < 8; nf++) {
                oacc[nf][0] *= a0; oacc[nf][1] *= a0;
                oacc[nf][2] *= a1; oacc[nf][3] *= a1;
            }

            __syncwarp();   // Ps rows warp-private: order stores before loads

            // ---- O += P V  (V fragments via ldmatrix.x4.trans) ----
            const uint32_t vbase = uS + (uint32_t)(4608 + buf * 9216 + km * AH + cm) * 2;
            #pragma unroll
            for (int ks = 0; ks < 4; ks++) {
                uint32_t a[4];
                const int pa = (wrow + gid) * AHW + ks * 8;
                const int pb = (wrow + gid + 8) * AHW + ks * 8;
                a[0] = Psw[pa + tig];     a[1] = Psw[pb + tig];
                a[2] = Psw[pa + tig + 4]; a[3] = Psw[pb + tig + 4];
                #pragma unroll
                for (int nfp = 0; nfp < 4; nfp++) {
                    uint32_t r0, r1, r2, r3;
                    const uint32_t addr = vbase + ks * (16 * AH * 2) + nfp * 32;
                    asm volatile(
                        "ldmatrix.sync.aligned.m8n8.x4.trans.shared.b16 {%0,%1,%2,%3}, [%4];"
                        : "=r"(r0), "=r"(r1), "=r"(r2), "=r"(r3) : "r"(addr));
                    uint32_t b0[2] = {r0, r1};
                    uint32_t b1[2] = {r2, r3};
                    mma_f16(oacc[nfp * 2],     a, b0);
                    mma_f16(oacc[nfp * 2 + 1], a, b1);
                }
            }
            __syncthreads();   // all reads of buf done before it is refilled
        }

        // ---- epilogue: normalize, write y as half ----
        const float inv0 = 1.f / l0;
        const float inv1 = 1.f / l1;
        __half* yp0 = y + (rowbase + row0g) * N_EMBED + hofs;
        __half* yp1 = y + (rowbase + row1g) * N_EMBED + hofs;
        #pragma unroll
        for (int nf = 0; nf < 8; nf++) {
            *reinterpret_cast<uint32_t*>(yp0 + nf * 8 + 2 * tig) =
                pack_h2(oacc[nf][0] * inv0, oacc[nf][1] * inv0);
            *reinterpret_cast<uint32_t*>(yp1 + nf * 8 + 2 * tig) =
                pack_h2(oacc[nf][2] * inv1, oacc[nf][3] * inv1);
        }
    }
}

// ---------------------------------------------------------------------------
// kernel_launch
// ---------------------------------------------------------------------------
extern "C" void kernel_launch(void* const* d_in, const int* in_sizes, int n_in,
                              void* d_out, int out_size) {
    const float* x      = (const float*)d_in[0];
    const float* W_attn = (const float*)d_in[1];
    const float* b_attn = (const float*)d_in[2];
    const float* W_proj = (const float*)d_in[3];
    const float* b_proj = (const float*)d_in[4];
    float* out = (float*)d_out;

    __half *qhp = nullptr, *khp = nullptr, *vhp = nullptr;
    __half *yh = nullptr, *xh = nullptr, *wa = nullptr, *wp = nullptr;
    int* work = nullptr;
    cudaGetSymbolAddress((void**)&qhp, g_qh);
    cudaGetSymbolAddress((void**)&khp, g_kh);
    cudaGetSymbolAddress((void**)&vhp, g_vh);
    cudaGetSymbolAddress((void**)&yh,  g_yh);
    cudaGetSymbolAddress((void**)&xh,  g_xh);
    cudaGetSymbolAddress((void**)&wa,  g_wa);
    cudaGetSymbolAddress((void**)&wp,  g_wp);
    cudaGetSymbolAddress((void**)&work, g_work);

    cudaFuncSetAttribute(mma_gemm_kernel,
                         cudaFuncAttributeMaxDynamicSharedMemorySize, G_SMEM_BYTES);
    cudaFuncSetAttribute(flash_attn_mma_kernel,
                         cudaFuncAttributeMaxDynamicSharedMemorySize, FA_SMEM_BYTES);

    // 0) Pre-convert: x -> half (and reset work counter); weights -> half ^T
    cvt_half_kernel<<<592, 256>>>(x, xh, MROWS * N_EMBED, work);
    {
        dim3 blk(32, 8);
        transpose_half_kernel<<<dim3(3 * N_EMBED / 32, N_EMBED / 32), blk>>>(
            W_attn, wa, N_EMBED, 3 * N_EMBED);
        transpose_half_kernel<<<dim3(N_EMBED / 32, N_EMBED / 32), blk>>>(
            W_proj, wp, N_EMBED, N_EMBED);
    }

    // 1) QKV GEMM -> half outputs (Q scaled 1/8, K, V)
    {
        dim3 grid(3 * N_EMBED / 128, MROWS / 128);
        mma_gemm_kernel<<<grid, 256, G_SMEM_BYTES>>>(
            xh, wa, b_attn, nullptr, qhp, khp, vhp,
            MROWS, 3 * N_EMBED, N_EMBED, 1);
    }
    // 2) Causal flash attention (persistent, dynamic heavy-first schedule)
    {
        flash_attn_mma_kernel<<<296, 128, FA_SMEM_BYTES>>>(qhp, khp, vhp, yh, work);
    }
    // 3) Output projection: y(half) @ Wproj^T(half) + b_proj -> fp32
    {
        dim3 grid(N_EMBED / 128, MROWS / 128);
        mma_gemm_kernel<<<grid, 256, G_SMEM_BYTES>>>(
            yh, wp, b_proj, out, nullptr, nullptr, nullptr,
            MROWS, N_EMBED, N_EMBED, 0);
    }
}

// round 17
// speedup vs baseline: 1.1480x; 1.1480x over previous
#include <cuda_runtime.h>
#include <cuda_fp16.h>
#include <math.h>
#include <stdint.h>

#define N_EMBED 1024
#define SLEN    2048
#define BATCH   4
#define NHEADS  16
#define HDIM    64
#define MROWS   (BATCH * SLEN)        // 8192

// Scratch (device globals: allocation-free rule)
__device__ __half g_qh[(size_t)MROWS * N_EMBED];        // Q half (scaled 1/8)
__device__ __half g_kh[(size_t)MROWS * N_EMBED];        // K half
__device__ __half g_vh[(size_t)MROWS * N_EMBED];        // V half
__device__ __half g_yh[(size_t)MROWS * N_EMBED];        // attention out half
__device__ __half g_xh[(size_t)MROWS * N_EMBED];        // x half
__device__ __half g_wa[(size_t)3 * N_EMBED * N_EMBED];  // Wattn^T half [3072,1024]
__device__ __half g_wp[(size_t)N_EMBED * N_EMBED];      // Wproj^T half [1024,1024]

// ---------------------------------------------------------------------------
// Helpers
// ---------------------------------------------------------------------------
__device__ __forceinline__ void mma_f16(float d[4], const uint32_t a[4], const uint32_t b[2]) {
    asm volatile(
        "mma.sync.aligned.m16n8k16.row.col.f32.f16.f16.f32 "
        "{%0,%1,%2,%3}, {%4,%5,%6,%7}, {%8,%9}, {%0,%1,%2,%3};"
        : "+f"(d[0]), "+f"(d[1]), "+f"(d[2]), "+f"(d[3])
        : "r"(a[0]), "r"(a[1]), "r"(a[2]), "r"(a[3]), "r"(b[0]), "r"(b[1]));
}
__device__ __forceinline__ uint32_t smem_u32(const void* p) {
    uint32_t a;
    asm("{ .reg .u64 t; cvta.to.shared.u64 t, %1; cvt.u32.u64 %0, t; }" : "=r"(a) : "l"(p));
    return a;
}
__device__ __forceinline__ void cp_async16(uint32_t saddr, const void* g) {
    asm volatile("cp.async.cg.shared.global [%0], [%1], 16;" :: "r"(saddr), "l"(g));
}
#define CP_COMMIT()  asm volatile("cp.async.commit_group;" ::: "memory")
#define CP_WAIT(n)   asm volatile("cp.async.wait_group %0;" :: "n"(n) : "memory")
__device__ __forceinline__ uint32_t pack_h2(float x, float y) {
    __half2 h = __floats2half2_rn(x, y);
    return *reinterpret_cast<uint32_t*>(&h);
}

// ---------------------------------------------------------------------------
// fp32 -> half elementwise (x), grid-stride.
// ---------------------------------------------------------------------------
__global__ __launch_bounds__(256)
void cvt_half_kernel(const float* __restrict__ in, __half* __restrict__ out, int n) {
    const int stride = gridDim.x * blockDim.x * 4;
    for (int i = (blockIdx.x * blockDim.x + threadIdx.x) * 4; i < n; i += stride) {
        float4 v = *reinterpret_cast<const float4*>(in + i);
        uint2 o;
        o.x = pack_h2(v.x, v.y);
        o.y = pack_h2(v.z, v.w);
        *reinterpret_cast<uint2*>(out + i) = o;
    }
}

// ---------------------------------------------------------------------------
// Transpose + cvt: out[c][r] = (half) in[r][c].
// ---------------------------------------------------------------------------
__global__ __launch_bounds__(256)
void transpose_half_kernel(const float* __restrict__ in, __half* __restrict__ out,
                           int R, int C) {
    __shared__ float t[32][33];
    const int c0 = blockIdx.x * 32, r0 = blockIdx.y * 32;
    const int tx = threadIdx.x, ty = threadIdx.y;   // 32 x 8
    #pragma unroll
    for (int i = ty; i < 32; i += 8)
        t[i][tx] = in[(size_t)(r0 + i) * C + c0 + tx];
    __syncthreads();
    #pragma unroll
    for (int i = ty; i < 32; i += 8)
        out[(size_t)(c0 + i) * R + r0 + tx] = __float2half_rn(t[tx][i]);
}

// ---------------------------------------------------------------------------
// fp16 mma.sync GEMM (R11-proven): C = A[M,K] @ Bt[N,K]^T + bias.
// mode 0: C fp32.  mode 1 (QKV): Q->qh (x1/8); K->kh; V->vh (all half).
// BM=BN=128, BK=32; 256 thr = 8 warps (2x4), warp tile 64x32; 4-stage cp.async.
// ---------------------------------------------------------------------------
#define G_RS 40
#define G_RSW 20
#define G_TSTG (128 * G_RS)
#define G_STG_HALFS (2 * G_TSTG)
#define G_SMEM_BYTES (4 * G_STG_HALFS * 2)

__global__ __launch_bounds__(256, 2)
void mma_gemm_kernel(const __half* __restrict__ A, const __half* __restrict__ Bt,
                     const float* __restrict__ bias, float* __restrict__ C,
                     __half* qh, __half* kh, __half* vh,
                     int M, int N, int K, int mode) {
    extern __shared__ uint32_t gsm[];

    const int tid   = threadIdx.x;
    const int lane  = tid & 31;
    const int wid   = tid >> 5;
    const int gid   = lane >> 2;
    const int tig   = lane & 3;
    const int warpM = wid >> 2;
    const int warpN = wid & 3;
    const int row0  = blockIdx.y * 128;
    const int col0  = blockIdx.x * 128;

    const uint32_t uS = smem_u32(gsm);
    const int lrow = tid >> 1;
    const int lch  = (tid & 1) * 2;

    auto issue = [&](int kt, int stg) {
        const __half* Ag = A  + (size_t)(row0 + lrow) * K + kt * 32;
        const __half* Bg = Bt + (size_t)(col0 + lrow) * K + kt * 32;
        const uint32_t sa = uS + (uint32_t)(stg * G_STG_HALFS + lrow * G_RS) * 2;
        const uint32_t sb = sa + (uint32_t)G_TSTG * 2;
        #pragma unroll
        for (int i = 0; i < 2; i++) {
            const int c = lch + i;
            cp_async16(sa + c * 16, Ag + c * 8);
            cp_async16(sb + c * 16, Bg + c * 8);
        }
        CP_COMMIT();
    };

    float acc[4][4][4];
    #pragma unroll
    for (int i = 0; i < 4; i++)
        #pragma unroll
        for (int j = 0; j < 4; j++)
            #pragma unroll
            for (int r = 0; r < 4; r++) acc[i][j][r] = 0.f;

    const int NT = K / 32;

    issue(0, 0); issue(1, 1); issue(2, 2);

    for (int kt = 0; kt < NT; kt++) {
        if (kt < NT - 2) { CP_WAIT(2); } else { CP_WAIT(0); }
        __syncthreads();

        const uint32_t* As = gsm + (kt & 3) * (G_STG_HALFS / 2);
        const uint32_t* Bs = As + (G_TSTG / 2);

        #pragma unroll
        for (int ks = 0; ks < 2; ks++) {
            const int kw = ks * 8;
            uint32_t a[4][4], b[4][2];
            #pragma unroll
            for (int mf = 0; mf < 4; mf++) {
                const int r = warpM * 64 + mf * 16;
                a[mf][0] = As[(r + gid)     * G_RSW + kw + tig];
                a[mf][1] = As[(r + gid + 8) * G_RSW + kw + tig];
                a[mf][2] = As[(r + gid)     * G_RSW + kw + tig + 4];
                a[mf][3] = As[(r + gid + 8) * G_RSW + kw + tig + 4];
            }
            #pragma unroll
            for (int nf = 0; nf < 4; nf++) {
                const int c = warpN * 32 + nf * 8 + gid;
                b[nf][0] = Bs[c * G_RSW + kw + tig];
                b[nf][1] = Bs[c * G_RSW + kw + tig + 4];
            }
            #pragma unroll
            for (int mf = 0; mf < 4; mf++)
                #pragma unroll
                for (int nf = 0; nf < 4; nf++)
                    mma_f16(acc[mf][nf], a[mf], b[nf]);
        }
        if (kt + 3 < NT) issue(kt + 3, (kt + 3) & 3);
    }

    #pragma unroll
    for (int mf = 0; mf < 4; mf++) {
        const size_t rb0 = (size_t)row0 + warpM * 64 + mf * 16 + gid;
        const size_t rb1 = rb0 + 8;
        #pragma unroll
        for (int nf = 0; nf < 4; nf++) {
            const int col = col0 + warpN * 32 + nf * 8 + tig * 2;
            const float2 bz = *reinterpret_cast<const float2*>(bias + col);
            const float o00 = acc[mf][nf][0] + bz.x, o01 = acc[mf][nf][1] + bz.y;
            const float o10 = acc[mf][nf][2] + bz.x, o11 = acc[mf][nf][3] + bz.y;
            if (mode == 0) {
                float2 v0, v1;
                v0.x = o00; v0.y = o01; v1.x = o10; v1.y = o11;
                *reinterpret_cast<float2*>(C + rb0 * N + col) = v0;
                *reinterpret_cast<float2*>(C + rb1 * N + col) = v1;
            } else if (col0 < 1024) {
                *reinterpret_cast<uint32_t*>(&qh[rb0 * N_EMBED + col]) =
                    pack_h2(o00 * 0.125f, o01 * 0.125f);
                *reinterpret_cast<uint32_t*>(&qh[rb1 * N_EMBED + col]) =
                    pack_h2(o10 * 0.125f, o11 * 0.125f);
            } else if (col0 < 2048) {
                const int c = col - 1024;
                *reinterpret_cast<uint32_t*>(&kh[rb0 * N_EMBED + c]) = pack_h2(o00, o01);
                *reinterpret_cast<uint32_t*>(&kh[rb1 * N_EMBED + c]) = pack_h2(o10, o11);
            } else {
                const int c = col - 2048;
                *reinterpret_cast<uint32_t*>(&vh[rb0 * N_EMBED + c]) = pack_h2(o00, o01);
                *reinterpret_cast<uint32_t*>(&vh[rb1 * N_EMBED + c]) = pack_h2(o10, o11);
            }
        }
    }
}

// ---------------------------------------------------------------------------
// Flash attention, fp16 MMAs (single-term QK), cp.async staging,
// ldmatrix.trans for V.  CTA = 128 q-rows (8 warps, 256 thr); 64-key chunks;
// 2 CTAs/SM. 1D grid of 1024 CTAs, heavy tiles first (HW backfill = LPT).
// SMEM halfs (rows of 72):
//   K0 @0 | V0 @4608 | K1 @9216 | V1 @13824 | Ps(128r) @18432  (27648 halfs)
//   Q overlay per tile: Qh @0 (over K0+V0, 128 rows).
// ---------------------------------------------------------------------------
#define AH 72
#define AHW 36
#define FA_SMEM_BYTES 55296

__global__ __launch_bounds__(256, 2)
void flash_attn_mma_kernel(const __half* __restrict__ qhg,
                           const __half* __restrict__ kh, const __half* __restrict__ vh,
                           __half* __restrict__ y) {
    extern __shared__ __half sh[];
    uint32_t* shw = reinterpret_cast<uint32_t*>(sh);
    const uint32_t uS = smem_u32(sh);

    const int idx = blockIdx.x;            // 0..1023
    const int qt  = 15 - (idx >> 6);       // heavy tiles first
    const int hb  = idx & 63;
    const int h   = hb & 15;
    const int b   = hb >> 4;
    const int tid = threadIdx.x;
    const int lane = tid & 31;
    const int wid  = tid >> 5;     // 0..7
    const int gid  = lane >> 2;
    const int tig  = lane & 3;
    const int q0   = qt * 128;
    const int wrow = wid * 16;     // 0..112
    const size_t rowbase = (size_t)b * SLEN;
    const int hofs = h * 64;
    const int nch  = 2 * qt + 2;

    // K/V staging: 64 rows, 256 threads -> 4 thr/row, 2x16B chunks each
    const int srow = tid >> 2;          // 0..63
    const int sck  = (tid & 3) * 2;     // chunk base 0,2,4,6
    // Q staging: 128 rows -> 2 thr/row, 4x16B chunks each
    const int qrow = tid >> 1;          // 0..127
    const int qck  = (tid & 1) * 4;

    uint32_t* Psw = shw + 9216;   // Ps word base (halfs offset 18432)

    // ldmatrix.trans lane-fixed addressing for V
    const int lm  = lane >> 3;
    const int lrw = lane & 7;
    const int km  = ((lm & 1) << 3) + lrw;
    const int cm  = (lm >> 1) * 8;

    // ---- Q staging (cp.async into overlay over K0+V0) ----
    {
        const __half* gq = qhg + (rowbase + q0 + qrow) * N_EMBED + hofs;
        const uint32_t dq = uS + (uint32_t)(qrow * AH) * 2;
        #pragma unroll
        for (int i = 0; i < 4; i++)
            cp_async16(dq + (qck + i) * 16, gq + (qck + i) * 8);
        CP_COMMIT();
        CP_WAIT(0);
    }
    __syncthreads();

    // ---- Q fragments (4 k16-steps over 64 dims) ----
    uint32_t qh[4][4];
    #pragma unroll
    for (int ks = 0; ks < 4; ks++) {
        const int ba = (wrow + gid) * AHW + ks * 8;
        const int bb = (wrow + gid + 8) * AHW + ks * 8;
        qh[ks][0] = shw[ba + tig];     qh[ks][1] = shw[bb + tig];
        qh[ks][2] = shw[ba + tig + 4]; qh[ks][3] = shw[bb + tig + 4];
    }
    __syncthreads();   // all warps done with overlay before K/V cp.async lands

    auto issue_kv = [&](int kb, int buf) {
        const __half* gk = kh + (rowbase + kb + srow) * N_EMBED + hofs;
        const __half* gv = vh + (rowbase + kb + srow) * N_EMBED + hofs;
        const uint32_t dk = uS + (uint32_t)(buf * 9216 + srow * AH) * 2;
        const uint32_t dv = dk + 4608 * 2;
        #pragma unroll
        for (int i = 0; i < 2; i++) {
            cp_async16(dk + (sck + i) * 16, gk + (sck + i) * 8);
            cp_async16(dv + (sck + i) * 16, gv + (sck + i) * 8);
        }
        CP_COMMIT();
    };

    issue_kv(0, 0);

    float oacc[8][4];
    #pragma unroll
    for (int nf = 0; nf < 8; nf++)
        #pragma unroll
        for (int e = 0; e < 4; e++) oacc[nf][e] = 0.f;
    float m0 = -INFINITY, m1 = -INFINITY, l0 = 0.f, l1 = 0.f;

    const int row0g = q0 + wrow + gid;
    const int row1g = row0g + 8;

    for (int i = 0; i < nch; i++) {
        const int buf = i & 1;
        const int kb  = i * 64;
        if (i + 1 < nch) { issue_kv(kb + 64, buf ^ 1); CP_WAIT(1); }
        else             { CP_WAIT(0); }
        __syncthreads();

        const uint32_t* Kw = shw + buf * 4608;

        // ---- S = Q K^T ----
        float sacc[8][4];
        #pragma unroll
        for (int nf = 0; nf < 8; nf++)
            #pragma unroll
            for (int e = 0; e < 4; e++) sacc[nf][e] = 0.f;

        #pragma unroll
        for (int ks = 0; ks < 4; ks++) {
            #pragma unroll
            for (int nf = 0; nf < 8; nf++) {
                const int kr = (nf * 8 + gid) * AHW + ks * 8;
                uint32_t bh[2];
                bh[0] = Kw[kr + tig]; bh[1] = Kw[kr + tig + 4];
                mma_f16(sacc[nf], qh[ks], bh);
            }
        }

        // ---- causal mask (diagonal/above chunks) ----
        if (kb + 63 > q0 + wrow) {
            #pragma unroll
            for (int nf = 0; nf < 8; nf++) {
                const int c = kb + nf * 8 + tig * 2;
                if (c     > row0g) sacc[nf][0] = -INFINITY;
                if (c + 1 > row0g) sacc[nf][1] = -INFINITY;
                if (c     > row1g) sacc[nf][2] = -INFINITY;
                if (c + 1 > row1g) sacc[nf][3] = -INFINITY;
            }
        }

        // ---- online softmax ----
        float mx0 = -INFINITY, mx1 = -INFINITY;
        #pragma unroll
        for (int nf = 0; nf < 8; nf++) {
            mx0 = fmaxf(mx0, fmaxf(sacc[nf][0], sacc[nf][1]));
            mx1 = fmaxf(mx1, fmaxf(sacc[nf][2], sacc[nf][3]));
        }
        mx0 = fmaxf(mx0, __shfl_xor_sync(0xffffffff, mx0, 1));
        mx0 = fmaxf(mx0, __shfl_xor_sync(0xffffffff, mx0, 2));
        mx1 = fmaxf(mx1, __shfl_xor_sync(0xffffffff, mx1, 1));
        mx1 = fmaxf(mx1, __shfl_xor_sync(0xffffffff, mx1, 2));

        const float mn0 = fmaxf(m0, mx0);
        const float mn1 = fmaxf(m1, mx1);
        const float a0 = __expf(m0 - mn0);
        const float a1 = __expf(m1 - mn1);
        m0 = mn0; m1 = mn1;

        float rs0 = 0.f, rs1 = 0.f;
        #pragma unroll
        for (int nf = 0; nf < 8; nf++) {
            const float p0 = __expf(sacc[nf][0] - m0);
            const float p1 = __expf(sacc[nf][1] - m0);
            const float p2 = __expf(sacc[nf][2] - m1);
            const float p3 = __expf(sacc[nf][3] - m1);
            rs0 += p0 + p1; rs1 += p2 + p3;
            Psw[(wrow + gid)     * AHW + nf * 4 + tig] = pack_h2(p0, p1);
            Psw[(wrow + gid + 8) * AHW + nf * 4 + tig] = pack_h2(p2, p3);
        }
        rs0 += __shfl_xor_sync(0xffffffff, rs0, 1);
        rs0 += __shfl_xor_sync(0xffffffff, rs0, 2);
        rs1 += __shfl_xor_sync(0xffffffff, rs1, 1);
        rs1 += __shfl_xor_sync(0xffffffff, rs1, 2);
        l0 = l0 * a0 + rs0;
        l1 = l1 * a1 + rs1;

        #pragma unroll
        for (int nf = 0; nf < 8; nf++) {
            oacc[nf][0] *= a0; oacc[nf][1] *= a0;
            oacc[nf][2] *= a1; oacc[nf][3] *= a1;
        }

        __syncwarp();   // Ps rows warp-private: order stores before loads

        // ---- O += P V  (V fragments via ldmatrix.x4.trans) ----
        const uint32_t vbase = uS + (uint32_t)(4608 + buf * 9216 + km * AH + cm) * 2;
        #pragma unroll
        for (int ks = 0; ks < 4; ks++) {
            uint32_t a[4];
            const int pa = (wrow + gid) * AHW + ks * 8;
            const int pb = (wrow + gid + 8) * AHW + ks * 8;
            a[0] = Psw[pa + tig];     a[1] = Psw[pb + tig];
            a[2] = Psw[pa + tig + 4]; a[3] = Psw[pb + tig + 4];
            #pragma unroll
            for (int nfp = 0; nfp < 4; nfp++) {
                uint32_t r0, r1, r2, r3;
                const uint32_t addr = vbase + ks * (16 * AH * 2) + nfp * 32;
                asm volatile(
                    "ldmatrix.sync.aligned.m8n8.x4.trans.shared.b16 {%0,%1,%2,%3}, [%4];"
                    : "=r"(r0), "=r"(r1), "=r"(r2), "=r"(r3) : "r"(addr));
                uint32_t b0[2] = {r0, r1};
                uint32_t b1[2] = {r2, r3};
                mma_f16(oacc[nfp * 2],     a, b0);
                mma_f16(oacc[nfp * 2 + 1], a, b1);
            }
        }
        __syncthreads();   // all reads of buf done before it is refilled
    }

    // ---- epilogue: normalize, write y as half ----
    const float inv0 = 1.f / l0;
    const float inv1 = 1.f / l1;
    __half* yp0 = y + (rowbase + row0g) * N_EMBED + hofs;
    __half* yp1 = y + (rowbase + row1g) * N_EMBED + hofs;
    #pragma unroll
    for (int nf = 0; nf < 8; nf++) {
        *reinterpret_cast<uint32_t*>(yp0 + nf * 8 + 2 * tig) =
            pack_h2(oacc[nf][0] * inv0, oacc[nf][1] * inv0);
        *reinterpret_cast<uint32_t*>(yp1 + nf * 8 + 2 * tig) =
            pack_h2(oacc[nf][2] * inv1, oacc[nf][3] * inv1);
    }
}

// ---------------------------------------------------------------------------
// kernel_launch
// ---------------------------------------------------------------------------
extern "C" void kernel_launch(void* const* d_in, const int* in_sizes, int n_in,
                              void* d_out, int out_size) {
    const float* x      = (const float*)d_in[0];
    const float* W_attn = (const float*)d_in[1];
    const float* b_attn = (const float*)d_in[2];
    const float* W_proj = (const float*)d_in[3];
    const float* b_proj = (const float*)d_in[4];
    float* out = (float*)d_out;

    __half *qhp = nullptr, *khp = nullptr, *vhp = nullptr;
    __half *yh = nullptr, *xh = nullptr, *wa = nullptr, *wp = nullptr;
    cudaGetSymbolAddress((void**)&qhp, g_qh);
    cudaGetSymbolAddress((void**)&khp, g_kh);
    cudaGetSymbolAddress((void**)&vhp, g_vh);
    cudaGetSymbolAddress((void**)&yh,  g_yh);
    cudaGetSymbolAddress((void**)&xh,  g_xh);
    cudaGetSymbolAddress((void**)&wa,  g_wa);
    cudaGetSymbolAddress((void**)&wp,  g_wp);

    cudaFuncSetAttribute(mma_gemm_kernel,
                         cudaFuncAttributeMaxDynamicSharedMemorySize, G_SMEM_BYTES);
    cudaFuncSetAttribute(flash_attn_mma_kernel,
                         cudaFuncAttributeMaxDynamicSharedMemorySize, FA_SMEM_BYTES);

    // 0) Pre-convert: x -> half; weights -> half transposed [N][K]
    cvt_half_kernel<<<592, 256>>>(x, xh, MROWS * N_EMBED);
    {
        dim3 blk(32, 8);
        transpose_half_kernel<<<dim3(3 * N_EMBED / 32, N_EMBED / 32), blk>>>(
            W_attn, wa, N_EMBED, 3 * N_EMBED);
        transpose_half_kernel<<<dim3(N_EMBED / 32, N_EMBED / 32), blk>>>(
            W_proj, wp, N_EMBED, N_EMBED);
    }

    // 1) QKV GEMM -> half outputs (Q scaled 1/8, K, V)
    {
        dim3 grid(3 * N_EMBED / 128, MROWS / 128);
        mma_gemm_kernel<<<grid, 256, G_SMEM_BYTES>>>(
            xh, wa, b_attn, nullptr, qhp, khp, vhp,
            MROWS, 3 * N_EMBED, N_EMBED, 1);
    }
    // 2) Causal flash attention (128-row tiles, heavy-first 1D grid)
    {
        flash_attn_mma_kernel<<<1024, 256, FA_SMEM_BYTES>>>(qhp, khp, vhp, yh);
    }
    // 3) Output projection: y(half) @ Wproj^T(half) + b_proj -> fp32
    {
        dim3 grid(N_EMBED / 128, MROWS / 128);
        mma_gemm_kernel<<<grid, 256, G_SMEM_BYTES>>>(
            yh, wp, b_proj, out, nullptr, nullptr, nullptr,
            MROWS, N_EMBED, N_EMBED, 0);
    }
}